// round 2
// baseline (speedup 1.0000x reference)
#include <cuda_runtime.h>
#include <math.h>

#define B_ 1024
#define C_ 10000
#define D_ 128
#define MAXH 32

// Scratch (no device allocation allowed -> __device__ globals)
__device__ int g_pseudo[2 * B_];      // pseudo_q (0..1023), pseudo_k (1024..2047)
__device__ int g_count[C_];           // hits per class (zeroed every replay in k_rank)
__device__ int g_hits[C_ * MAXH];     // hit item indices per class, rank-ordered

// ---------------------------------------------------------------------------
// Kernel 1: per-row weighted argmax for output_q and output_k, fused with the
// pass-through copies of output_q, output_k and q. One block per row.
// ---------------------------------------------------------------------------
__global__ void __launch_bounds__(256) k_argmax_copy(
    const float* __restrict__ oq, const float* __restrict__ ok,
    const float* __restrict__ pY, const float* __restrict__ q,
    float* __restrict__ out)
{
    const int row = blockIdx.x;
    const int t   = threadIdx.x;

    const float4* oq4 = (const float4*)(oq + (size_t)row * C_);
    const float4* ok4 = (const float4*)(ok + (size_t)row * C_);
    const float4* pY4 = (const float4*)(pY + (size_t)row * C_);
    float4* o0 = (float4*)(out + (size_t)row * C_);
    float4* o1 = (float4*)(out + (size_t)B_ * C_ + (size_t)row * C_);

    float bq = -INFINITY, bk = -INFINITY;
    int   iq = 0,         ik = 0;

    // C_/4 = 2500 float4 per row
    for (int i = t; i < C_ / 4; i += 256) {
        float4 y = pY4[i];
        float4 a = oq4[i];
        float4 b = ok4[i];
        o0[i] = a;            // copy output_q
        o1[i] = b;            // copy output_k
        int base = i * 4;
        // weight is exactly 1.0 (candidate) or 0.1 (non-candidate)
        {
            float w = (y.x != 0.f) ? 1.f : 0.1f;
            float vq = a.x * w, vk = b.x * w;
            if (vq > bq) { bq = vq; iq = base + 0; }
            if (vk > bk) { bk = vk; ik = base + 0; }
        }
        {
            float w = (y.y != 0.f) ? 1.f : 0.1f;
            float vq = a.y * w, vk = b.y * w;
            if (vq > bq) { bq = vq; iq = base + 1; }
            if (vk > bk) { bk = vk; ik = base + 1; }
        }
        {
            float w = (y.z != 0.f) ? 1.f : 0.1f;
            float vq = a.z * w, vk = b.z * w;
            if (vq > bq) { bq = vq; iq = base + 2; }
            if (vk > bk) { bk = vk; ik = base + 2; }
        }
        {
            float w = (y.w != 0.f) ? 1.f : 0.1f;
            float vq = a.w * w, vk = b.w * w;
            if (vq > bq) { bq = vq; iq = base + 3; }
            if (vk > bk) { bk = vk; ik = base + 3; }
        }
    }

    // copy q row (128 floats = 32 float4) while reductions proceed
    if (t < 32) {
        const float4* q4 = (const float4*)(q + (size_t)row * D_);
        float4* oc = (float4*)(out + 6ull * B_ * C_ + (size_t)row * D_);
        oc[t] = q4[t];
    }

    __shared__ float sv[256];
    __shared__ int   si[256];

    // reduce argmax for q (first-index tie-break)
    sv[t] = bq; si[t] = iq;
    __syncthreads();
    for (int s = 128; s > 0; s >>= 1) {
        if (t < s) {
            float v = sv[t + s]; int j = si[t + s];
            if (v > sv[t] || (v == sv[t] && j < si[t])) { sv[t] = v; si[t] = j; }
        }
        __syncthreads();
    }
    if (t == 0) g_pseudo[row] = si[0];
    __syncthreads();

    // reduce argmax for k
    sv[t] = bk; si[t] = ik;
    __syncthreads();
    for (int s = 128; s > 0; s >>= 1) {
        if (t < s) {
            float v = sv[t + s]; int j = si[t + s];
            if (v > sv[t] || (v == sv[t] && j < si[t])) { sv[t] = v; si[t] = j; }
        }
        __syncthreads();
    }
    if (t == 0) g_pseudo[B_ + row] = si[0];
}

// ---------------------------------------------------------------------------
// Kernel 2: one fp32 SIMT GEMM for all four logit products.
// Virtual A = [q; k; q_mix; k_mix] : [4096, 128], B = prototypes [10000, 128],
// out[m, n] = dot(A[m], P[n]); out is the contiguous 4*B*C logits region.
// BM=128, BN=128, BK=16, 256 threads, 8x8 per thread.
// ---------------------------------------------------------------------------
#define BM 128
#define BN 128
#define BK 16

__global__ void __launch_bounds__(256) k_gemm(
    const float* __restrict__ q,  const float* __restrict__ k,
    const float* __restrict__ qm, const float* __restrict__ km,
    const float* __restrict__ P,  float* __restrict__ out)
{
    __shared__ float As[BK][BM + 4];
    __shared__ float Bs[BK][BN + 4];

    const int n0 = blockIdx.x * BN;
    const int m0 = blockIdx.y * BM;

    const int sel = m0 >> 10;   // 128 | 1024 -> whole block in one source
    const float* src = (sel == 0) ? q : (sel == 1) ? k : (sel == 2) ? qm : km;
    const int mloc = m0 & 1023;

    const int t  = threadIdx.x;
    const int tx = t & 15;      // n direction
    const int ty = t >> 4;      // m direction

    float acc[8][8];
#pragma unroll
    for (int i = 0; i < 8; i++)
#pragma unroll
        for (int j = 0; j < 8; j++) acc[i][j] = 0.f;

    for (int kt = 0; kt < D_; kt += BK) {
        // Load A tile: 128 rows x 16 k = 512 float4
#pragma unroll
        for (int l = t; l < 512; l += 256) {
            int r  = l >> 2;
            int kq = l & 3;
            float4 v = *(const float4*)(src + (size_t)(mloc + r) * D_ + kt + kq * 4);
            As[kq * 4 + 0][r] = v.x;
            As[kq * 4 + 1][r] = v.y;
            As[kq * 4 + 2][r] = v.z;
            As[kq * 4 + 3][r] = v.w;
        }
        // Load B tile (guard rows >= C_)
#pragma unroll
        for (int l = t; l < 512; l += 256) {
            int r  = l >> 2;
            int kq = l & 3;
            float4 v = make_float4(0.f, 0.f, 0.f, 0.f);
            if (n0 + r < C_)
                v = *(const float4*)(P + (size_t)(n0 + r) * D_ + kt + kq * 4);
            Bs[kq * 4 + 0][r] = v.x;
            Bs[kq * 4 + 1][r] = v.y;
            Bs[kq * 4 + 2][r] = v.z;
            Bs[kq * 4 + 3][r] = v.w;
        }
        __syncthreads();

#pragma unroll
        for (int kk = 0; kk < BK; kk++) {
            float4 a0 = *(const float4*)&As[kk][ty * 8];
            float4 a1 = *(const float4*)&As[kk][ty * 8 + 4];
            float4 b0 = *(const float4*)&Bs[kk][tx * 8];
            float4 b1 = *(const float4*)&Bs[kk][tx * 8 + 4];
            float a[8] = {a0.x, a0.y, a0.z, a0.w, a1.x, a1.y, a1.z, a1.w};
            float b[8] = {b0.x, b0.y, b0.z, b0.w, b1.x, b1.y, b1.z, b1.w};
#pragma unroll
            for (int i = 0; i < 8; i++)
#pragma unroll
                for (int j = 0; j < 8; j++)
                    acc[i][j] = fmaf(a[i], b[j], acc[i][j]);
        }
        __syncthreads();
    }

    // Store
    const bool full = (n0 + BN <= C_);
#pragma unroll
    for (int i = 0; i < 8; i++) {
        int m = m0 + ty * 8 + i;
        float* orow = out + (size_t)m * C_ + n0 + tx * 8;
        if (full) {
            *(float4*)(orow)     = make_float4(acc[i][0], acc[i][1], acc[i][2], acc[i][3]);
            *(float4*)(orow + 4) = make_float4(acc[i][4], acc[i][5], acc[i][6], acc[i][7]);
        } else {
#pragma unroll
            for (int j = 0; j < 8; j++)
                if (n0 + tx * 8 + j < C_) orow[j] = acc[i][j];
        }
    }
}

// ---------------------------------------------------------------------------
// Kernel 3: per-item rank among same-label items (combined order: q samples
// 0..1023 then k samples 0..1023 — exactly the reference scan order).
// Single block; also zeroes g_count each replay (determinism).
// ---------------------------------------------------------------------------
__global__ void __launch_bounds__(1024) k_rank()
{
    __shared__ int labs[2 * B_];
    const int t = threadIdx.x;
    labs[t]       = g_pseudo[t];
    labs[t + B_]  = g_pseudo[t + B_];
    for (int c = t; c < C_; c += 1024) g_count[c] = 0;
    __syncthreads();

    for (int i = t; i < 2 * B_; i += 1024) {
        int lab = labs[i];
        int r = 0;
        int j = 0;
        for (; j + 4 <= i; j += 4) {
            r += (labs[j + 0] == lab);
            r += (labs[j + 1] == lab);
            r += (labs[j + 2] == lab);
            r += (labs[j + 3] == lab);
        }
        for (; j < i; j++) r += (labs[j] == lab);
        if (r < MAXH) g_hits[lab * MAXH + r] = i;
        atomicAdd(&g_count[lab], 1);
    }
}

// ---------------------------------------------------------------------------
// Kernel 4: per-class EMA replay (exact reference recurrence, in order) +
// L2 normalize. One warp per class, float4 per lane (128 = 32*4).
// ---------------------------------------------------------------------------
__global__ void __launch_bounds__(256) k_ema(
    const float* __restrict__ protos, const float* __restrict__ q,
    const float* __restrict__ k, float* __restrict__ outp)
{
    const int c    = (blockIdx.x * blockDim.x + threadIdx.x) >> 5;
    const int lane = threadIdx.x & 31;
    if (c >= C_) return;

    float4 p = ((const float4*)(protos + (size_t)c * D_))[lane];
    int m = g_count[c];
    if (m > MAXH) m = MAXH;   // never triggers for these shapes; OOB guard only

    for (int r = 0; r < m; r++) {
        int j = g_hits[c * MAXH + r];
        const float* f = (j < B_) ? (q + (size_t)j * D_) : (k + (size_t)(j - B_) * D_);
        float4 fv = ((const float4*)f)[lane];
        p.x = p.x * 0.99f + 0.01f * fv.x;
        p.y = p.y * 0.99f + 0.01f * fv.y;
        p.z = p.z * 0.99f + 0.01f * fv.z;
        p.w = p.w * 0.99f + 0.01f * fv.w;
    }

    float ss = p.x * p.x + p.y * p.y + p.z * p.z + p.w * p.w;
#pragma unroll
    for (int o = 16; o > 0; o >>= 1) ss += __shfl_xor_sync(0xffffffffu, ss, o);
    float nrm = sqrtf(ss);
    float d = fmaxf(nrm, 1e-12f);
    p.x /= d; p.y /= d; p.z /= d; p.w /= d;
    ((float4*)(outp + (size_t)c * D_))[lane] = p;
}

// ---------------------------------------------------------------------------
// Launch. Input order (metadata): output_q, output_k, q, k, q_mix, k_mix,
// partial_Y, prototypes. Output layout: [output_q | output_k | logits_q |
// logits_k | logits_q_mix | logits_k_mix | q | new_p], all fp32.
// ---------------------------------------------------------------------------
extern "C" void kernel_launch(void* const* d_in, const int* in_sizes, int n_in,
                              void* d_out, int out_size)
{
    const float* oq = (const float*)d_in[0];
    const float* ok = (const float*)d_in[1];
    const float* q  = (const float*)d_in[2];
    const float* k  = (const float*)d_in[3];
    const float* qm = (const float*)d_in[4];
    const float* km = (const float*)d_in[5];
    const float* pY = (const float*)d_in[6];
    const float* P  = (const float*)d_in[7];
    float* out = (float*)d_out;

    k_argmax_copy<<<B_, 256>>>(oq, ok, pY, q, out);
    k_gemm<<<dim3((C_ + BN - 1) / BN, (4 * B_) / BM), 256>>>(
        q, k, qm, km, P, out + 2ull * B_ * C_);
    k_rank<<<1, 1024>>>();
    k_ema<<<(C_ + 7) / 8, 256>>>(P, q, k, out + 6ull * B_ * C_ + (size_t)B_ * D_);
}

// round 9
// speedup vs baseline: 1.5439x; 1.5439x over previous
#include <cuda_runtime.h>
#include <cuda_bf16.h>
#include <mma.h>
#include <math.h>

using namespace nvcuda;

__device__ int g_ps[2048];
__device__ int g_cnt[10000];
__device__ int g_hit[320000];
__device__ __nv_bfloat16 g_Ah[524288];
__device__ __nv_bfloat16 g_Al[524288];
__device__ __nv_bfloat16 g_Ph[1294336];
__device__ __nv_bfloat16 g_Pl[1294336];

__global__ void __launch_bounds__(256) k1(const float* oq, const float* ok,
    const float* pY, const float* q, float* out)
{
  int row = blockIdx.x, t = threadIdx.x;
  const float4* a4 = (const float4*)(oq + (size_t)row * 10000);
  const float4* b4 = (const float4*)(ok + (size_t)row * 10000);
  const float4* y4 = (const float4*)(pY + (size_t)row * 10000);
  float4* o0 = (float4*)(out + (size_t)row * 10000);
  float4* o1 = (float4*)(out + 10240000ull + (size_t)row * 10000);
  float bq = -INFINITY, bk = -INFINITY;
  int iq = 0, ik = 0;
  for (int i = t; i < 2500; i += 256) {
    float4 y = y4[i], a = a4[i], b = b4[i];
    o0[i] = a;
    o1[i] = b;
    float w0 = y.x != 0.f ? 1.f : 0.1f;
    float w1 = y.y != 0.f ? 1.f : 0.1f;
    float w2 = y.z != 0.f ? 1.f : 0.1f;
    float w3 = y.w != 0.f ? 1.f : 0.1f;
    float va0 = a.x * w0, va1 = a.y * w1, va2 = a.z * w2, va3 = a.w * w3;
    float vb0 = b.x * w0, vb1 = b.y * w1, vb2 = b.z * w2, vb3 = b.w * w3;
    if (va0 > bq) { bq = va0; iq = i * 4; }
    if (va1 > bq) { bq = va1; iq = i * 4 + 1; }
    if (va2 > bq) { bq = va2; iq = i * 4 + 2; }
    if (va3 > bq) { bq = va3; iq = i * 4 + 3; }
    if (vb0 > bk) { bk = vb0; ik = i * 4; }
    if (vb1 > bk) { bk = vb1; ik = i * 4 + 1; }
    if (vb2 > bk) { bk = vb2; ik = i * 4 + 2; }
    if (vb3 > bk) { bk = vb3; ik = i * 4 + 3; }
  }
  if (t < 32) {
    const float4* q4 = (const float4*)(q + (size_t)row * 128);
    float4* oc = (float4*)(out + 61440000ull + (size_t)row * 128);
    oc[t] = q4[t];
  }
  __shared__ float sv[256];
  __shared__ int si[256];
  sv[t] = bq; si[t] = iq;
  __syncthreads();
  for (int s = 128; s > 0; s >>= 1) {
    if (t < s) {
      float v = sv[t + s]; int j = si[t + s];
      if (v > sv[t] || (v == sv[t] && j < si[t])) { sv[t] = v; si[t] = j; }
    }
    __syncthreads();
  }
  if (t == 0) g_ps[row] = si[0];
  __syncthreads();
  sv[t] = bk; si[t] = ik;
  __syncthreads();
  for (int s = 128; s > 0; s >>= 1) {
    if (t < s) {
      float v = sv[t + s]; int j = si[t + s];
      if (v > sv[t] || (v == sv[t] && j < si[t])) { sv[t] = v; si[t] = j; }
    }
    __syncthreads();
  }
  if (t == 0) g_ps[1024 + row] = si[0];
}

__device__ __forceinline__ void sp4(float4 v, __nv_bfloat162* dh, __nv_bfloat162* dl)
{
  __nv_bfloat16 h0 = __float2bfloat16_rn(v.x), h1 = __float2bfloat16_rn(v.y);
  __nv_bfloat16 h2 = __float2bfloat16_rn(v.z), h3 = __float2bfloat16_rn(v.w);
  __nv_bfloat16 l0 = __float2bfloat16_rn(v.x - __bfloat162float(h0));
  __nv_bfloat16 l1 = __float2bfloat16_rn(v.y - __bfloat162float(h1));
  __nv_bfloat16 l2 = __float2bfloat16_rn(v.z - __bfloat162float(h2));
  __nv_bfloat16 l3 = __float2bfloat16_rn(v.w - __bfloat162float(h3));
  dh[0] = __halves2bfloat162(h0, h1);
  dh[1] = __halves2bfloat162(h2, h3);
  dl[0] = __halves2bfloat162(l0, l1);
  dl[1] = __halves2bfloat162(l2, l3);
}

__global__ void __launch_bounds__(256) k2(const float* q, const float* k,
    const float* qm, const float* km, const float* P)
{
  int i = blockIdx.x * 256 + threadIdx.x;
  if (i < 131072) {
    int s = i >> 15;
    const float4* sp = s == 0 ? (const float4*)q : s == 1 ? (const float4*)k :
                       s == 2 ? (const float4*)qm : (const float4*)km;
    sp4(sp[i & 32767], (__nv_bfloat162*)g_Ah + (size_t)i * 2,
        (__nv_bfloat162*)g_Al + (size_t)i * 2);
  } else if (i < 451072) {
    int e = i - 131072;
    sp4(((const float4*)P)[e], (__nv_bfloat162*)g_Ph + (size_t)e * 2,
        (__nv_bfloat162*)g_Pl + (size_t)e * 2);
  } else if (i < 454656) {
    int e = i - 131072;
    sp4(make_float4(0.f, 0.f, 0.f, 0.f), (__nv_bfloat162*)g_Ph + (size_t)e * 2,
        (__nv_bfloat162*)g_Pl + (size_t)e * 2);
  }
}

__global__ void __launch_bounds__(256) k3(float* out)
{
  __shared__ __nv_bfloat16 sAh[5120];
  __shared__ __nv_bfloat16 sAl[5120];
  __shared__ __nv_bfloat16 sBh[2560];
  __shared__ __nv_bfloat16 sBl[2560];

  int t = threadIdx.x;
  int bn = blockIdx.x * 64, bm = blockIdx.y * 128;
  int wid = t >> 5;
  int wm = (wid & 3) * 32;
  int wn = (wid >> 2) * 32;

  wmma::fragment<wmma::accumulator, 16, 16, 16, float> acc[2][2];
  for (int i = 0; i < 2; i++)
    for (int j = 0; j < 2; j++)
      wmma::fill_fragment(acc[i][j], 0.0f);

  for (int kc = 0; kc < 128; kc += 32) {
    __syncthreads();
    for (int i = t; i < 512; i += 256) {
      int r = i >> 2, c = (i & 3) * 8;
      *(float4*)(sAh + r * 40 + c) =
          *(const float4*)(g_Ah + (size_t)(bm + r) * 128 + kc + c);
      *(float4*)(sAl + r * 40 + c) =
          *(const float4*)(g_Al + (size_t)(bm + r) * 128 + kc + c);
    }
    {
      int r = t >> 2, c = (t & 3) * 8;
      if (r < 64) {
        *(float4*)(sBh + r * 40 + c) =
            *(const float4*)(g_Ph + (size_t)(bn + r) * 128 + kc + c);
        *(float4*)(sBl + r * 40 + c) =
            *(const float4*)(g_Pl + (size_t)(bn + r) * 128 + kc + c);
      }
    }
    __syncthreads();
    for (int kk = 0; kk < 32; kk += 16) {
      wmma::fragment<wmma::matrix_a, 16, 16, 16, __nv_bfloat16, wmma::row_major> ah[2], al[2];
      wmma::fragment<wmma::matrix_b, 16, 16, 16, __nv_bfloat16, wmma::col_major> bh[2], bl[2];
      for (int i = 0; i < 2; i++) {
        wmma::load_matrix_sync(ah[i], sAh + (wm + i * 16) * 40 + kk, 40);
        wmma::load_matrix_sync(al[i], sAl + (wm + i * 16) * 40 + kk, 40);
        wmma::load_matrix_sync(bh[i], sBh + (wn + i * 16) * 40 + kk, 40);
        wmma::load_matrix_sync(bl[i], sBl + (wn + i * 16) * 40 + kk, 40);
      }
      for (int i = 0; i < 2; i++)
        for (int j = 0; j < 2; j++) {
          wmma::mma_sync(acc[i][j], ah[i], bh[j], acc[i][j]);
          wmma::mma_sync(acc[i][j], ah[i], bl[j], acc[i][j]);
          wmma::mma_sync(acc[i][j], al[i], bh[j], acc[i][j]);
        }
    }
  }

  for (int i = 0; i < 2; i++)
    for (int j = 0; j < 2; j++) {
      int cc = bn + wn + j * 16;
      if (cc < 10000) {
        int rr = bm + wm + i * 16;
        wmma::store_matrix_sync(out + (size_t)rr * 10000 + cc, acc[i][j],
                                10000, wmma::mem_row_major);
      }
    }
}

__global__ void __launch_bounds__(1024) k5()
{
  __shared__ int lb[2048];
  int t = threadIdx.x;
  lb[t] = g_ps[t];
  lb[t + 1024] = g_ps[t + 1024];
  for (int c = t; c < 10000; c += 1024) g_cnt[c] = 0;
  __syncthreads();
  for (int i = t; i < 2048; i += 1024) {
    int la = lb[i], r = 0;
    for (int j = 0; j < i; j++) r += (lb[j] == la);
    if (r < 32) g_hit[la * 32 + r] = i;
    atomicAdd(&g_cnt[la], 1);
  }
}

__global__ void __launch_bounds__(256) k4(const float* pr, const float* q,
    const float* k, float* op)
{
  int c = (blockIdx.x * 256 + threadIdx.x) >> 5, ln = threadIdx.x & 31;
  if (c >= 10000) return;
  float4 pv = ((const float4*)(pr + (size_t)c * 128))[ln];
  float p0 = pv.x, p1 = pv.y, p2 = pv.z, p3 = pv.w;
  int m = g_cnt[c];
  if (m > 32) m = 32;
  for (int r = 0; r < m; r++) {
    int j = g_hit[c * 32 + r];
    const float* f = j < 1024 ? q + (size_t)j * 128 : k + (size_t)(j - 1024) * 128;
    float4 fv = ((const float4*)f)[ln];
    p0 = p0 * 0.99f + 0.01f * fv.x;
    p1 = p1 * 0.99f + 0.01f * fv.y;
    p2 = p2 * 0.99f + 0.01f * fv.z;
    p3 = p3 * 0.99f + 0.01f * fv.w;
  }
  float ss = p0 * p0 + p1 * p1 + p2 * p2 + p3 * p3;
  for (int o = 16; o > 0; o >>= 1) ss += __shfl_xor_sync(0xffffffffu, ss, o);
  float dn = fmaxf(sqrtf(ss), 1e-12f);
  float4 w = make_float4(p0 / dn, p1 / dn, p2 / dn, p3 / dn);
  ((float4*)(op + (size_t)c * 128))[ln] = w;
}

extern "C" void kernel_launch(void* const* d_in, const int* in_sizes, int n_in,
                              void* d_out, int out_size)
{
  const float* oq = (const float*)d_in[0];
  const float* ok = (const float*)d_in[1];
  const float* q  = (const float*)d_in[2];
  const float* k  = (const float*)d_in[3];
  const float* qm = (const float*)d_in[4];
  const float* km = (const float*)d_in[5];
  const float* pY = (const float*)d_in[6];
  const float* P  = (const float*)d_in[7];
  float* out = (float*)d_out;
  k2<<<1776, 256>>>(q, k, qm, km, P);
  k1<<<1024, 256>>>(oq, ok, pY, q, out);
  k3<<<dim3(158, 32), 256>>>(out + 20480000ull);
  k5<<<1, 1024>>>();
  k4<<<1250, 256>>>(P, q, k, out + 61571072ull);
}

// round 10
// speedup vs baseline: 1.6689x; 1.0809x over previous
#include <cuda_runtime.h>
#include <cuda_bf16.h>
#include <mma.h>
#include <math.h>

using namespace nvcuda;

__device__ int g_ps[2048];
__device__ int g_cnt[10000];
__device__ int g_hit[320000];
__device__ __nv_bfloat16 g_Ah[524288];
__device__ __nv_bfloat16 g_Al[524288];
__device__ __nv_bfloat16 g_Ph[1294336];
__device__ __nv_bfloat16 g_Pl[1294336];

__global__ void __launch_bounds__(256) k1(const float* oq, const float* ok,
    const float* pY, const float* q, float* out)
{
  int row = blockIdx.x, t = threadIdx.x;
  const float4* a4 = (const float4*)(oq + (size_t)row * 10000);
  const float4* b4 = (const float4*)(ok + (size_t)row * 10000);
  const float4* y4 = (const float4*)(pY + (size_t)row * 10000);
  float4* o0 = (float4*)(out + (size_t)row * 10000);
  float4* o1 = (float4*)(out + 10240000ull + (size_t)row * 10000);
  float bq = -INFINITY, bk = -INFINITY;
  int iq = 0, ik = 0;
  for (int i = t; i < 2500; i += 256) {
    float4 y = y4[i], a = a4[i], b = b4[i];
    o0[i] = a;
    o1[i] = b;
    float w0 = y.x != 0.f ? 1.f : 0.1f;
    float w1 = y.y != 0.f ? 1.f : 0.1f;
    float w2 = y.z != 0.f ? 1.f : 0.1f;
    float w3 = y.w != 0.f ? 1.f : 0.1f;
    float va0 = a.x * w0, va1 = a.y * w1, va2 = a.z * w2, va3 = a.w * w3;
    float vb0 = b.x * w0, vb1 = b.y * w1, vb2 = b.z * w2, vb3 = b.w * w3;
    if (va0 > bq) { bq = va0; iq = i * 4; }
    if (va1 > bq) { bq = va1; iq = i * 4 + 1; }
    if (va2 > bq) { bq = va2; iq = i * 4 + 2; }
    if (va3 > bq) { bq = va3; iq = i * 4 + 3; }
    if (vb0 > bk) { bk = vb0; ik = i * 4; }
    if (vb1 > bk) { bk = vb1; ik = i * 4 + 1; }
    if (vb2 > bk) { bk = vb2; ik = i * 4 + 2; }
    if (vb3 > bk) { bk = vb3; ik = i * 4 + 3; }
  }
  if (t < 32) {
    const float4* q4 = (const float4*)(q + (size_t)row * 128);
    float4* oc = (float4*)(out + 61440000ull + (size_t)row * 128);
    oc[t] = q4[t];
  }
  __shared__ float sv[256];
  __shared__ int si[256];
  sv[t] = bq; si[t] = iq;
  __syncthreads();
  for (int s = 128; s > 0; s >>= 1) {
    if (t < s) {
      float v = sv[t + s]; int j = si[t + s];
      if (v > sv[t] || (v == sv[t] && j < si[t])) { sv[t] = v; si[t] = j; }
    }
    __syncthreads();
  }
  if (t == 0) g_ps[row] = si[0];
  __syncthreads();
  sv[t] = bk; si[t] = ik;
  __syncthreads();
  for (int s = 128; s > 0; s >>= 1) {
    if (t < s) {
      float v = sv[t + s]; int j = si[t + s];
      if (v > sv[t] || (v == sv[t] && j < si[t])) { sv[t] = v; si[t] = j; }
    }
    __syncthreads();
  }
  if (t == 0) g_ps[1024 + row] = si[0];
}

__device__ __forceinline__ void sp4(float4 v, __nv_bfloat162* dh, __nv_bfloat162* dl)
{
  __nv_bfloat16 h0 = __float2bfloat16_rn(v.x), h1 = __float2bfloat16_rn(v.y);
  __nv_bfloat16 h2 = __float2bfloat16_rn(v.z), h3 = __float2bfloat16_rn(v.w);
  __nv_bfloat16 l0 = __float2bfloat16_rn(v.x - __bfloat162float(h0));
  __nv_bfloat16 l1 = __float2bfloat16_rn(v.y - __bfloat162float(h1));
  __nv_bfloat16 l2 = __float2bfloat16_rn(v.z - __bfloat162float(h2));
  __nv_bfloat16 l3 = __float2bfloat16_rn(v.w - __bfloat162float(h3));
  dh[0] = __halves2bfloat162(h0, h1);
  dh[1] = __halves2bfloat162(h2, h3);
  dl[0] = __halves2bfloat162(l0, l1);
  dl[1] = __halves2bfloat162(l2, l3);
}

__global__ void __launch_bounds__(256) k2(const float* q, const float* k,
    const float* qm, const float* km, const float* P)
{
  int i = blockIdx.x * 256 + threadIdx.x;
  if (i < 10000) g_cnt[i] = 0;
  if (i < 131072) {
    int s = i >> 15;
    const float4* sp = s == 0 ? (const float4*)q : s == 1 ? (const float4*)k :
                       s == 2 ? (const float4*)qm : (const float4*)km;
    sp4(sp[i & 32767], (__nv_bfloat162*)g_Ah + (size_t)i * 2,
        (__nv_bfloat162*)g_Al + (size_t)i * 2);
  } else if (i < 451072) {
    int e = i - 131072;
    sp4(((const float4*)P)[e], (__nv_bfloat162*)g_Ph + (size_t)e * 2,
        (__nv_bfloat162*)g_Pl + (size_t)e * 2);
  } else if (i < 454656) {
    int e = i - 131072;
    sp4(make_float4(0.f, 0.f, 0.f, 0.f), (__nv_bfloat162*)g_Ph + (size_t)e * 2,
        (__nv_bfloat162*)g_Pl + (size_t)e * 2);
  }
}

__global__ void __launch_bounds__(256, 2) k3(float* out)
{
  extern __shared__ __nv_bfloat16 sm[];
  __nv_bfloat16* sAh = sm;
  __nv_bfloat16* sAl = sm + 17408;
  __nv_bfloat16* sBh = sm + 34816;
  __nv_bfloat16* sBl = sm + 43520;

  int t = threadIdx.x;
  int bn = blockIdx.x * 64, bm = blockIdx.y * 128;
  int wid = t >> 5;
  int wm = (wid & 3) * 32;
  int wn = (wid >> 2) * 32;

  for (int i = t; i < 2048; i += 256) {
    int r = i >> 4, c = (i & 15) * 8;
    *(float4*)(sAh + r * 136 + c) =
        *(const float4*)(g_Ah + (size_t)(bm + r) * 128 + c);
    *(float4*)(sAl + r * 136 + c) =
        *(const float4*)(g_Al + (size_t)(bm + r) * 128 + c);
  }
  for (int i = t; i < 1024; i += 256) {
    int r = i >> 4, c = (i & 15) * 8;
    *(float4*)(sBh + r * 136 + c) =
        *(const float4*)(g_Ph + (size_t)(bn + r) * 128 + c);
    *(float4*)(sBl + r * 136 + c) =
        *(const float4*)(g_Pl + (size_t)(bn + r) * 128 + c);
  }

  wmma::fragment<wmma::accumulator, 16, 16, 16, float> acc[2][2];
  for (int i = 0; i < 2; i++)
    for (int j = 0; j < 2; j++)
      wmma::fill_fragment(acc[i][j], 0.0f);

  __syncthreads();

  for (int kk = 0; kk < 128; kk += 16) {
    wmma::fragment<wmma::matrix_a, 16, 16, 16, __nv_bfloat16, wmma::row_major> ah[2], al[2];
    wmma::fragment<wmma::matrix_b, 16, 16, 16, __nv_bfloat16, wmma::col_major> bh[2], bl[2];
    for (int i = 0; i < 2; i++) {
      wmma::load_matrix_sync(ah[i], sAh + (wm + i * 16) * 136 + kk, 136);
      wmma::load_matrix_sync(al[i], sAl + (wm + i * 16) * 136 + kk, 136);
      wmma::load_matrix_sync(bh[i], sBh + (wn + i * 16) * 136 + kk, 136);
      wmma::load_matrix_sync(bl[i], sBl + (wn + i * 16) * 136 + kk, 136);
    }
    for (int i = 0; i < 2; i++)
      for (int j = 0; j < 2; j++) {
        wmma::mma_sync(acc[i][j], ah[i], bh[j], acc[i][j]);
        wmma::mma_sync(acc[i][j], ah[i], bl[j], acc[i][j]);
        wmma::mma_sync(acc[i][j], al[i], bh[j], acc[i][j]);
      }
  }

  for (int i = 0; i < 2; i++)
    for (int j = 0; j < 2; j++) {
      int cc = bn + wn + j * 16;
      if (cc < 10000) {
        int rr = bm + wm + i * 16;
        wmma::store_matrix_sync(out + (size_t)rr * 10000 + cc, acc[i][j],
                                10000, wmma::mem_row_major);
      }
    }
}

__global__ void __launch_bounds__(256) k5()
{
  int w = blockIdx.x * 8 + (threadIdx.x >> 5);
  int ln = threadIdx.x & 31;
  int lab = g_ps[w];
  int r = 0;
  for (int j = 0; j < w; j += 32) {
    int jj = j + ln;
    int lj = jj < w ? g_ps[jj] : -1;
    unsigned m = __ballot_sync(0xffffffffu, lj == lab);
    r += __popc(m);
  }
  if (ln == 0) {
    if (r < 32) g_hit[lab * 32 + r] = w;
    atomicAdd(&g_cnt[lab], 1);
  }
}

__global__ void __launch_bounds__(256) k4(const float* pr, const float* q,
    const float* k, float* op)
{
  int c = (blockIdx.x * 256 + threadIdx.x) >> 5, ln = threadIdx.x & 31;
  if (c >= 10000) return;
  float4 pv = ((const float4*)(pr + (size_t)c * 128))[ln];
  float p0 = pv.x, p1 = pv.y, p2 = pv.z, p3 = pv.w;
  int m = g_cnt[c];
  if (m > 32) m = 32;
  for (int r = 0; r < m; r++) {
    int j = g_hit[c * 32 + r];
    const float* f = j < 1024 ? q + (size_t)j * 128 : k + (size_t)(j - 1024) * 128;
    float4 fv = ((const float4*)f)[ln];
    p0 = p0 * 0.99f + 0.01f * fv.x;
    p1 = p1 * 0.99f + 0.01f * fv.y;
    p2 = p2 * 0.99f + 0.01f * fv.z;
    p3 = p3 * 0.99f + 0.01f * fv.w;
  }
  float ss = p0 * p0 + p1 * p1 + p2 * p2 + p3 * p3;
  for (int o = 16; o > 0; o >>= 1) ss += __shfl_xor_sync(0xffffffffu, ss, o);
  float dn = fmaxf(sqrtf(ss), 1e-12f);
  float4 w = make_float4(p0 / dn, p1 / dn, p2 / dn, p3 / dn);
  ((float4*)(op + (size_t)c * 128))[ln] = w;
}

extern "C" void kernel_launch(void* const* d_in, const int* in_sizes, int n_in,
                              void* d_out, int out_size)
{
  const float* oq = (const float*)d_in[0];
  const float* ok = (const float*)d_in[1];
  const float* q  = (const float*)d_in[2];
  const float* k  = (const float*)d_in[3];
  const float* qm = (const float*)d_in[4];
  const float* km = (const float*)d_in[5];
  const float* pY = (const float*)d_in[6];
  const float* P  = (const float*)d_in[7];
  float* out = (float*)d_out;
  cudaFuncSetAttribute(k3, cudaFuncAttributeMaxDynamicSharedMemorySize, 104448);
  k2<<<1776, 256>>>(q, k, qm, km, P);
  k1<<<1024, 256>>>(oq, ok, pY, q, out);
  k3<<<dim3(158, 32), 256, 104448>>>(out + 20480000ull);
  k5<<<256, 256>>>();
  k4<<<1250, 256>>>(P, q, k, out + 61571072ull);
}

// round 12
// speedup vs baseline: 1.8280x; 1.0953x over previous
#include <cuda_runtime.h>
#include <cuda_bf16.h>
#include <cuda_pipeline.h>
#include <mma.h>
#include <math.h>

using namespace nvcuda;

__device__ int g_ps[2048];
__device__ int g_cnt[10000];
__device__ int g_hit[320000];
__device__ __nv_bfloat16 g_Ah[524288];
__device__ __nv_bfloat16 g_Al[524288];
__device__ __nv_bfloat16 g_Ph[1294336];
__device__ __nv_bfloat16 g_Pl[1294336];

__global__ void __launch_bounds__(256) k1(const float* oq, const float* ok,
    const float* pY, const float* q, float* out)
{
  int row = blockIdx.x, t = threadIdx.x;
  const float4* a4 = (const float4*)(oq + (size_t)row * 10000);
  const float4* b4 = (const float4*)(ok + (size_t)row * 10000);
  const float4* y4 = (const float4*)(pY + (size_t)row * 10000);
  float4* o0 = (float4*)(out + (size_t)row * 10000);
  float4* o1 = (float4*)(out + 10240000ull + (size_t)row * 10000);
  float bq = -INFINITY, bk = -INFINITY;
  int iq = 0, ik = 0;
  for (int i = t; i < 2500; i += 256) {
    float4 y = y4[i], a = a4[i], b = b4[i];
    o0[i] = a;
    o1[i] = b;
    float w0 = y.x != 0.f ? 1.f : 0.1f;
    float w1 = y.y != 0.f ? 1.f : 0.1f;
    float w2 = y.z != 0.f ? 1.f : 0.1f;
    float w3 = y.w != 0.f ? 1.f : 0.1f;
    float va0 = a.x * w0, va1 = a.y * w1, va2 = a.z * w2, va3 = a.w * w3;
    float vb0 = b.x * w0, vb1 = b.y * w1, vb2 = b.z * w2, vb3 = b.w * w3;
    if (va0 > bq) { bq = va0; iq = i * 4; }
    if (va1 > bq) { bq = va1; iq = i * 4 + 1; }
    if (va2 > bq) { bq = va2; iq = i * 4 + 2; }
    if (va3 > bq) { bq = va3; iq = i * 4 + 3; }
    if (vb0 > bk) { bk = vb0; ik = i * 4; }
    if (vb1 > bk) { bk = vb1; ik = i * 4 + 1; }
    if (vb2 > bk) { bk = vb2; ik = i * 4 + 2; }
    if (vb3 > bk) { bk = vb3; ik = i * 4 + 3; }
  }
  if (t < 32) {
    const float4* q4 = (const float4*)(q + (size_t)row * 128);
    float4* oc = (float4*)(out + 61440000ull + (size_t)row * 128);
    oc[t] = q4[t];
  }
  __shared__ float sv[256];
  __shared__ int si[256];
  sv[t] = bq; si[t] = iq;
  __syncthreads();
  for (int s = 128; s > 0; s >>= 1) {
    if (t < s) {
      float v = sv[t + s]; int j = si[t + s];
      if (v > sv[t] || (v == sv[t] && j < si[t])) { sv[t] = v; si[t] = j; }
    }
    __syncthreads();
  }
  if (t == 0) g_ps[row] = si[0];
  __syncthreads();
  sv[t] = bk; si[t] = ik;
  __syncthreads();
  for (int s = 128; s > 0; s >>= 1) {
    if (t < s) {
      float v = sv[t + s]; int j = si[t + s];
      if (v > sv[t] || (v == sv[t] && j < si[t])) { sv[t] = v; si[t] = j; }
    }
    __syncthreads();
  }
  if (t == 0) g_ps[1024 + row] = si[0];
}

__device__ __forceinline__ void sp4(float4 v, __nv_bfloat162* dh, __nv_bfloat162* dl)
{
  __nv_bfloat16 h0 = __float2bfloat16_rn(v.x), h1 = __float2bfloat16_rn(v.y);
  __nv_bfloat16 h2 = __float2bfloat16_rn(v.z), h3 = __float2bfloat16_rn(v.w);
  __nv_bfloat16 l0 = __float2bfloat16_rn(v.x - __bfloat162float(h0));
  __nv_bfloat16 l1 = __float2bfloat16_rn(v.y - __bfloat162float(h1));
  __nv_bfloat16 l2 = __float2bfloat16_rn(v.z - __bfloat162float(h2));
  __nv_bfloat16 l3 = __float2bfloat16_rn(v.w - __bfloat162float(h3));
  dh[0] = __halves2bfloat162(h0, h1);
  dh[1] = __halves2bfloat162(h2, h3);
  dl[0] = __halves2bfloat162(l0, l1);
  dl[1] = __halves2bfloat162(l2, l3);
}

__global__ void __launch_bounds__(256) k2(const float* q, const float* k,
    const float* qm, const float* km, const float* P)
{
  int i = blockIdx.x * 256 + threadIdx.x;
  if (i < 10000) g_cnt[i] = 0;
  if (i < 131072) {
    int s = i >> 15;
    const float4* sp = s == 0 ? (const float4*)q : s == 1 ? (const float4*)k :
                       s == 2 ? (const float4*)qm : (const float4*)km;
    sp4(sp[i & 32767], (__nv_bfloat162*)g_Ah + (size_t)i * 2,
        (__nv_bfloat162*)g_Al + (size_t)i * 2);
  } else if (i < 451072) {
    int e = i - 131072;
    sp4(((const float4*)P)[e], (__nv_bfloat162*)g_Ph + (size_t)e * 2,
        (__nv_bfloat162*)g_Pl + (size_t)e * 2);
  } else if (i < 454656) {
    int e = i - 131072;
    sp4(make_float4(0.f, 0.f, 0.f, 0.f), (__nv_bfloat162*)g_Ph + (size_t)e * 2,
        (__nv_bfloat162*)g_Pl + (size_t)e * 2);
  }
}

__global__ void __launch_bounds__(256) k3(float* out)
{
  extern __shared__ __nv_bfloat16 sm[];
  int t = threadIdx.x;
  int bn = blockIdx.x * 128, bm = blockIdx.y * 128;
  int wid = t >> 5;
  int wm = (wid >> 2) * 64;
  int wn = (wid & 3) * 32;

  const __nv_bfloat16* gA0 = g_Ah + (size_t)bm * 128;
  const __nv_bfloat16* gA1 = g_Al + (size_t)bm * 128;
  const __nv_bfloat16* gB0 = g_Ph + (size_t)bn * 128;
  const __nv_bfloat16* gB1 = g_Pl + (size_t)bn * 128;

  for (int st = 0; st < 2; st++) {
    int kc = st * 32;
    for (int i = t; i < 2048; i += 256) {
      int a = i >> 9, idx = i & 511;
      int r = idx >> 2, c = (idx & 3) * 8;
      const __nv_bfloat16* src =
          (a == 0 ? gA0 : a == 1 ? gA1 : a == 2 ? gB0 : gB1)
          + (size_t)r * 128 + kc + c;
      __pipeline_memcpy_async(sm + st * 20480 + a * 5120 + r * 40 + c, src, 16);
    }
    __pipeline_commit();
  }

  wmma::fragment<wmma::accumulator, 16, 16, 16, float> acc[4][2];
  for (int i = 0; i < 4; i++)
    for (int j = 0; j < 2; j++)
      wmma::fill_fragment(acc[i][j], 0.0f);

  for (int kc = 0; kc < 4; kc++) {
    if (kc >= 2) __pipeline_wait_prior(0);
    else __pipeline_wait_prior(1);
    __syncthreads();
    __nv_bfloat16* sAh = sm + (kc & 1) * 20480;
    __nv_bfloat16* sAl = sAh + 5120;
    __nv_bfloat16* sBh = sAh + 10240;
    __nv_bfloat16* sBl = sAh + 15360;
    for (int kk = 0; kk < 32; kk += 16) {
      wmma::fragment<wmma::matrix_b, 16, 16, 16, __nv_bfloat16, wmma::col_major> bh[2], bl[2];
      for (int j = 0; j < 2; j++) {
        wmma::load_matrix_sync(bh[j], sBh + (wn + j * 16) * 40 + kk, 40);
        wmma::load_matrix_sync(bl[j], sBl + (wn + j * 16) * 40 + kk, 40);
      }
      for (int mt = 0; mt < 4; mt++) {
        wmma::fragment<wmma::matrix_a, 16, 16, 16, __nv_bfloat16, wmma::row_major> ah, al;
        wmma::load_matrix_sync(ah, sAh + (wm + mt * 16) * 40 + kk, 40);
        wmma::load_matrix_sync(al, sAl + (wm + mt * 16) * 40 + kk, 40);
        for (int j = 0; j < 2; j++) {
          wmma::mma_sync(acc[mt][j], ah, bh[j], acc[mt][j]);
          wmma::mma_sync(acc[mt][j], ah, bl[j], acc[mt][j]);
          wmma::mma_sync(acc[mt][j], al, bh[j], acc[mt][j]);
        }
      }
    }
    __syncthreads();
    if (kc + 2 < 4) {
      int kn = (kc + 2) * 32;
      for (int i = t; i < 2048; i += 256) {
        int a = i >> 9, idx = i & 511;
        int r = idx >> 2, c = (idx & 3) * 8;
        const __nv_bfloat16* src =
            (a == 0 ? gA0 : a == 1 ? gA1 : a == 2 ? gB0 : gB1)
            + (size_t)r * 128 + kn + c;
        __pipeline_memcpy_async(sm + (kc & 1) * 20480 + a * 5120 + r * 40 + c, src, 16);
      }
      __pipeline_commit();
    }
  }

  for (int mt = 0; mt < 4; mt++)
    for (int j = 0; j < 2; j++) {
      int cc = bn + wn + j * 16;
      if (cc < 10000) {
        int rr = bm + wm + mt * 16;
        wmma::store_matrix_sync(out + (size_t)rr * 10000 + cc, acc[mt][j],
                                10000, wmma::mem_row_major);
      }
    }
}

__global__ void __launch_bounds__(256) k5()
{
  __shared__ int lb[2048];
  int t = threadIdx.x;
  for (int i = t; i < 2048; i += 256) lb[i] = g_ps[i];
  __syncthreads();
  int wid = t >> 5, ln = t & 31;
  for (int it = 0; it < 4; it++) {
    int w = (blockIdx.x * 8 + wid) * 4 + it;
    int lab = lb[w];
    int r = 0;
    for (int j = 0; j < w; j += 32) {
      int jj = j + ln;
      int lj = jj < w ? lb[jj] : -1;
      unsigned m = __ballot_sync(0xffffffffu, lj == lab);
      r += __popc(m);
    }
    if (ln == 0) {
      if (r < 32) g_hit[lab * 32 + r] = w;
      atomicAdd(&g_cnt[lab], 1);
    }
  }
}

__global__ void __launch_bounds__(256) k4(const float* pr, const float* q,
    const float* k, float* op)
{
  int c = (blockIdx.x * 256 + threadIdx.x) >> 5, ln = threadIdx.x & 31;
  if (c >= 10000) return;
  float4 pv = ((const float4*)(pr + (size_t)c * 128))[ln];
  float p0 = pv.x, p1 = pv.y, p2 = pv.z, p3 = pv.w;
  int m = g_cnt[c];
  if (m > 32) m = 32;
  for (int r = 0; r < m; r++) {
    int j = g_hit[c * 32 + r];
    const float* f = j < 1024 ? q + (size_t)j * 128 : k + (size_t)(j - 1024) * 128;
    float4 fv = ((const float4*)f)[ln];
    p0 = p0 * 0.99f + 0.01f * fv.x;
    p1 = p1 * 0.99f + 0.01f * fv.y;
    p2 = p2 * 0.99f + 0.01f * fv.z;
    p3 = p3 * 0.99f + 0.01f * fv.w;
  }
  float ss = p0 * p0 + p1 * p1 + p2 * p2 + p3 * p3;
  for (int o = 16; o > 0; o >>= 1) ss += __shfl_xor_sync(0xffffffffu, ss, o);
  float dn = fmaxf(sqrtf(ss), 1e-12f);
  float4 w = make_float4(p0 / dn, p1 / dn, p2 / dn, p3 / dn);
  ((float4*)(op + (size_t)c * 128))[ln] = w;
}

extern "C" void kernel_launch(void* const* d_in, const int* in_sizes, int n_in,
                              void* d_out, int out_size)
{
  const float* oq = (const float*)d_in[0];
  const float* ok = (const float*)d_in[1];
  const float* q  = (const float*)d_in[2];
  const float* k  = (const float*)d_in[3];
  const float* qm = (const float*)d_in[4];
  const float* km = (const float*)d_in[5];
  const float* pY = (const float*)d_in[6];
  const float* P  = (const float*)d_in[7];
  float* out = (float*)d_out;
  cudaFuncSetAttribute(k3, cudaFuncAttributeMaxDynamicSharedMemorySize, 81920);
  k2<<<1776, 256>>>(q, k, qm, km, P);
  k1<<<1024, 256>>>(oq, ok, pY, q, out);
  k3<<<dim3(79, 32), 256, 81920>>>(out + 20480000ull);
  k5<<<64, 256>>>();
  k4<<<1250, 256>>>(P, q, k, out + 61571072ull);
}